// round 17
// baseline (speedup 1.0000x reference)
#include <cuda_runtime.h>
#include <cuda_bf16.h>
#include <cstdint>

// Problem constants
#define BB   64     // batch
#define NP   900    // predictions (columns)
#define NCLS 128    // classes
#define MT   64     // targets (rows)
#define KC   8      // corners
#define INF_F 1000000000.0f

#define TBLK  128   // threads per block (both roles)
#define NPK   8     // ceil(900/128) columns per LSA thread
#define NTILE 32    // n-tile per cost block
#define NTPB  29    // cost tiles per batch  (29*32 >= 900)

// Transposed cost scratch: CT[b][m][n], contiguous in n for fast row reads.
__device__ float g_CT[(size_t)BB * MT * NP];
// Per-(b,m) INVERTED packed row min (atomicMax over inverted == min). Zero-init;
// consumer lsa block resets to 0 after use (idempotent across graph replays).
__device__ unsigned long long g_rowmin[BB * MT];
// Per-batch completion counters (cost blocks done). Reset by lsa block.
__device__ int g_done[BB];

// ---------------------------------------------------------------------------
// Order-preserving float <-> u32 encoding for unsigned-min reductions.
// ---------------------------------------------------------------------------
__device__ __forceinline__ unsigned fenc(float f) {
    unsigned u = __float_as_uint(f);
    return u ^ (unsigned)(((int)u >> 31) | 0x80000000);
}
__device__ __forceinline__ float fdec(unsigned e) {
    unsigned u = (e & 0x80000000u) ? (e ^ 0x80000000u) : ~e;
    return __uint_as_float(u);
}

// ---------------------------------------------------------------------------
// Mega-kernel: blocks [0, BB) are per-batch LSA consumers (spin on g_done);
// blocks [BB, BB + BB*NTPB) are cost producers (batch-major: early batches
// finish first, so early consumers start early).
// ---------------------------------------------------------------------------
__global__ __launch_bounds__(TBLK, 1)
void mega_kernel(const float* __restrict__ logits,
                 const float* __restrict__ corners,
                 const int*   __restrict__ labels,
                 const float* __restrict__ boxes,
                 float* __restrict__ out) {
    const int tid  = threadIdx.x;
    const int lane = tid & 31;
    const int wid  = tid >> 5;

    if (blockIdx.x >= BB) {
        // ================= COST PRODUCER =================
        const int idx = blockIdx.x - BB;
        const int b   = idx / NTPB;
        const int n0  = (idx % NTPB) * NTILE;

        __shared__ float tile[MT][NTILE + 1];
        __shared__ float sh_probs[4][NCLS];
        __shared__ float sh_cen[4][3];
        __shared__ int   sh_lab[MT];
        __shared__ float sh_box[MT][3];

        if (n0 == 0 && tid < MT) {
            float* tgtf = out + (size_t)BB * NP * MT + (size_t)BB * MT;
            tgtf[b * MT + tid] = (float)tid;
        }

        if (tid < MT) {
            sh_lab[tid] = labels[b * MT + tid];
            const float* bx = boxes + ((size_t)b * MT + tid) * 7;
            sh_box[tid][0] = bx[0];
            sh_box[tid][1] = bx[1];
            sh_box[tid][2] = bx[2];
        }
        __syncthreads();

        #pragma unroll
        for (int q = 0; q < 8; q++) {
            int n = n0 + wid * 8 + q;
            if (n < NP) {
                const float* lg = logits + ((size_t)b * NP + n) * NCLS;
                float l0 = lg[lane], l1 = lg[lane + 32], l2 = lg[lane + 64], l3 = lg[lane + 96];
                float mx = fmaxf(fmaxf(l0, l1), fmaxf(l2, l3));
                #pragma unroll
                for (int o = 16; o; o >>= 1) mx = fmaxf(mx, __shfl_xor_sync(0xffffffffu, mx, o));
                float e0 = expf(l0 - mx), e1 = expf(l1 - mx), e2 = expf(l2 - mx), e3 = expf(l3 - mx);
                float s = e0 + e1 + e2 + e3;
                #pragma unroll
                for (int o = 16; o; o >>= 1) s += __shfl_xor_sync(0xffffffffu, s, o);
                sh_probs[wid][lane]      = e0 / s;
                sh_probs[wid][lane + 32] = e1 / s;
                sh_probs[wid][lane + 64] = e2 / s;
                sh_probs[wid][lane + 96] = e3 / s;

                const float* cr = corners + ((size_t)b * NP + n) * (KC * 3);
                if (lane < 3) {
                    float sum = 0.0f;
                    #pragma unroll
                    for (int k = 0; k < KC; k++) sum += cr[k * 3 + lane];
                    sh_cen[wid][lane] = sum * 0.125f;
                }
                __syncwarp();
                float cx = sh_cen[wid][0], cy = sh_cen[wid][1], cz = sh_cen[wid][2];

                #pragma unroll
                for (int t = 0; t < 2; t++) {
                    int m = lane + t * 32;
                    float cc = -sh_probs[wid][sh_lab[m]];
                    float dx = cx - sh_box[m][0], dy = cy - sh_box[m][1], dz = cz - sh_box[m][2];
                    float c = cc + 5.0f * sqrtf(dx * dx + dy * dy + dz * dz);
                    out[((size_t)b * NP + n) * MT + m] = c;
                    tile[m][n - n0] = c;
                }
            }
        }
        __syncthreads();

        // coalesced CT writes: warp writes a 128B row segment per iteration
        {
            const int  n   = n0 + lane;
            const bool nok = (n < NP);
            #pragma unroll
            for (int r = 0; r < 16; r++) {
                int m = wid * 16 + r;
                if (nok) g_CT[((size_t)b * MT + m) * NP + n] = tile[m][lane];
            }
        }

        // fused per-row packed min: tid<64 scans its row of the tile.
        if (tid < MT) {
            const int cmax = (NP - n0 < NTILE) ? (NP - n0) : NTILE;
            unsigned long long x = 0xFFFFFFFFFFFFFFFFull;
            #pragma unroll
            for (int c = 0; c < NTILE; c++) {
                if (c < cmax) {
                    unsigned long long y =
                        ((unsigned long long)fenc(tile[tid][c]) << 32) | (unsigned)(n0 + c);
                    if (y < x) x = y;
                }
            }
            atomicMax(&g_rowmin[b * MT + tid], ~x);
        }
        __syncthreads();

        // publish completion (release)
        if (tid == 0) {
            __threadfence();
            atomicAdd(&g_done[b], 1);
        }
        return;
    }

    // ================= LSA CONSUMER (batch b) =================
    const int b = blockIdx.x;

    __shared__ int                p_sh[NP + 1];
    __shared__ float              u_sh[NP + 1];    // u_of_col[j] == u[p_sh[j]]
    __shared__ int                way_sh[NP + 1];
    __shared__ float              umin_sh[MT];
    __shared__ int                jmin_sh[MT];
    __shared__ int                ua_sh[MT];
    __shared__ int                nua_sh;
    __shared__ unsigned long long redbuf[2][4];
    __shared__ unsigned long long pubuf[2][4];

    // producer-independent init (overlaps the spin)
    for (int j = tid; j <= NP; j += TBLK) { p_sh[j] = 0; u_sh[j] = 0.0f; }

    // spin until this batch's 29 cost blocks are done (acquire loads)
    if (tid == 0) {
        int d;
        do {
            asm volatile("ld.global.acquire.gpu.b32 %0, [%1];"
                         : "=r"(d) : "l"(&g_done[b]) : "memory");
        } while (d < NTPB);
    }
    __syncthreads();

    if (tid < MT) {
        unsigned long long x = ~g_rowmin[b * MT + tid];
        umin_sh[tid] = fdec((unsigned)(x >> 32));
        jmin_sh[tid] = (int)(unsigned)x;           // 0-based column
    }

    const float* CT = g_CT + (size_t)b * MT * NP;

    // fire-and-forget L1 prime: 1800 x 128B lines, ~14 prefetches per thread
    {
        const char* base = (const char*)CT;
        const int nlines = (MT * NP * 4 + 127) / 128;
        for (int i = tid; i < nlines; i += TBLK) {
            asm volatile("prefetch.global.L1 [%0];" :: "l"(base + (size_t)i * 128));
        }
    }
    __syncthreads();

    if (tid == 0) {
        // greedy prefill (serial, tiny)
        int nun = 0;
        for (int i = 0; i < MT; i++) {
            int j1 = jmin_sh[i] + 1;
            if (p_sh[j1] == 0) { p_sh[j1] = i + 1; u_sh[j1] = umin_sh[i]; }
            else ua_sh[nun++] = i + 1;
        }
        nua_sh = nun;
    }
    __syncthreads();

    const int  nua   = nua_sh;
    const int  jbase = 1 + tid;
    const bool v7    = (tid < NP - 7 * TBLK);   // tid < 4 -> k=7 valid

    float v[NPK], ureg[NPK], minv[NPK];
    int   preg[NPK];
    #pragma unroll
    for (int k = 0; k < NPK; k++) v[k] = 0.0f;

    // ---- exact shortest-augmenting-path for collided rows (R9 verbatim) ----
    for (int t = 0; t < nua; t++) {
        const int i1 = ua_sh[t];

        #pragma unroll
        for (int k = 0; k < NPK; k++) {
            bool valid = (k < NPK - 1) | v7;
            if (valid) {
                preg[k] = p_sh[jbase + TBLK * k];
                ureg[k] = u_sh[jbase + TBLK * k];
            }
            minv[k] = INF_F;
        }
        unsigned usedm = 0;
        float u0col = umin_sh[i1 - 1];     // feasible u for row i1
        float pend  = 0.0f;
        float u0    = u0col;
        int   j0    = 0, i0 = i1;
        if (tid == 0) p_sh[0] = i1;

        for (int it = 0; it < MT + 8; it++) {
            if (i0 == 0) break;

            unsigned newm = usedm;
            if (j0 > 0 && ((j0 - 1) & (TBLK - 1)) == tid)
                newm |= 1u << ((j0 - 1) >> 7);

            const float* rp = CT + (size_t)(i0 - 1) * NP + tid;

            // batch the row loads first (MLP), then compute
            float cvals[NPK];
            #pragma unroll
            for (int k = 0; k < NPK; k++) {
                bool valid = (k < NPK - 1) | v7;
                if (valid) cvals[k] = rp[TBLK * k];
            }

            unsigned bestenc = 0xFFFFFFFFu;
            int      bestj   = 0x7FFFFFFF;
            int      bestp   = 0;
            float    bestu   = 0.0f;
            #pragma unroll
            for (int k = 0; k < NPK; k++) {
                bool valid = (k < NPK - 1) | v7;
                if (valid) {
                    int j = jbase + TBLK * k;
                    if ((usedm >> k) & 1) { v[k] -= pend; ureg[k] += pend; }
                    else                  minv[k] -= pend;
                    float cur = cvals[k] - u0 - v[k];
                    bool isused = (newm >> k) & 1;
                    if (!isused && cur < minv[k]) { minv[k] = cur; way_sh[j] = j0; }
                    float mv = isused ? INF_F : minv[k];
                    unsigned enc = fenc(mv);
                    if (enc < bestenc) {
                        bestenc = enc; bestj = j; bestp = preg[k]; bestu = ureg[k];
                    }
                }
            }
            u0col += pend;
            usedm  = newm;

            // warp argmin via single redux; winner lane = lowest tied lane
            unsigned wenc = __reduce_min_sync(0xffffffffu, bestenc);
            unsigned ball = __ballot_sync(0xffffffffu, bestenc == wenc);
            if (lane == __ffs(ball) - 1) {
                redbuf[it & 1][wid] = ((unsigned long long)wenc << 32)
                                      | (unsigned)bestj;
                pubuf [it & 1][wid] = ((unsigned long long)(unsigned)bestp << 32)
                                      | __float_as_uint(bestu);
            }
            __syncthreads();

            const unsigned long long* rb = redbuf[it & 1];
            const unsigned long long* pb = pubuf[it & 1];
            unsigned long long b0 = rb[0], b1 = rb[1], b2 = rb[2], b3 = rb[3];
            unsigned long long q0 = pb[0], q1 = pb[1], q2 = pb[2], q3 = pb[3];
            if (b1 < b0) { b0 = b1; q0 = q1; }
            if (b3 < b2) { b2 = b3; q2 = q3; }
            if (b2 < b0) { b0 = b2; q0 = q2; }

            j0   = (int)(unsigned)b0;
            pend = fdec((unsigned)(b0 >> 32));
            i0   = (int)(q0 >> 32);
            u0   = __uint_as_float((unsigned)q0);
        }

        #pragma unroll
        for (int k = 0; k < NPK; k++) {
            bool valid = (k < NPK - 1) | v7;
            if (valid && ((usedm >> k) & 1)) {
                v[k]    -= pend;
                ureg[k] += pend;
                u_sh[jbase + TBLK * k] = ureg[k];
            }
        }
        u0col += pend;
        if (tid == 0) u_sh[0] = u0col;
        __syncthreads();

        if (tid == 0) {
            int jj = j0;
            for (int s = 0; s < MT + 8 && jj != 0; s++) {
                int jn = way_sh[jj];
                p_sh[jj] = p_sh[jn];
                u_sh[jj] = u_sh[jn];
                jj = jn;
            }
        }
        __syncthreads();
    }

    // outputs: pred_idx (value-cast float)
    float* predf = out + (size_t)BB * NP * MT;
    for (int j = 1 + tid; j <= NP; j += TBLK) {
        int r = p_sh[j];
        if (r > 0) predf[b * MT + (r - 1)] = (float)(j - 1);
    }

    // reset per-batch state for the next call (idempotent across replays)
    if (tid < MT) g_rowmin[b * MT + tid] = 0ull;
    if (tid == 0) g_done[b] = 0;
}

// ---------------------------------------------------------------------------
extern "C" void kernel_launch(void* const* d_in, const int* in_sizes, int n_in,
                              void* d_out, int out_size) {
    const float* logits  = (const float*)d_in[0];   // [64, 900, 128]
    const float* corners = (const float*)d_in[1];   // [64, 900, 8, 3]
    const int*   labels  = (const int*)  d_in[2];   // [64, 64]
    const float* boxes   = (const float*)d_in[3];   // [64, 64, 7]
    float* out = (float*)d_out;

    (void)in_sizes; (void)n_in; (void)out_size;

    // 64 lsa consumer blocks first (resident early), then 1856 cost producers
    mega_kernel<<<BB + BB * NTPB, TBLK>>>(logits, corners, labels, boxes, out);
}